// round 11
// baseline (speedup 1.0000x reference)
#include <cuda_runtime.h>
#include <cuda_fp16.h>
#include <cstdint>
#include <math.h>

// ---------------- problem constants ----------------
#define BDIM   4096          // batch rows
#define KDIM   4096          // F + S
#define NGATE  6144          // 3*S
#define SDIM   2048
#define HSIZE  8388608L      // B*S

// ---------------- scheme ----------------
// X = A0 + A1 (fp16 + residual), W^T = B0 + B1.
// main:  A0*B0 -> f32 acc (m16n8k16.f16)
// corr:  A1q*B0q + A0q*B1q -> ONE s32 acc (m16n8k32.s8), shared scale:
//   A1q = s8(SA1*a1), B0q = s8(SB0*b0), A0q = s8(SA0*a0), B1q = s8(SB1*b1)
//   SA1 = SB1 = 57344, SA0 = SB0 = 20  ->  both products scale 1/1146880
#define SA1F 57344.0f
#define SA0F 20.0f
#define INV_S 8.7193e-7f     // 1/(57344*20)

#define BM 128
#define BNS 32               // state-cols per CTA; B tile = 3 gates x 32 = 96 rows
#define BNROWS 96
#define BK 32                // 2 fp16 k16 slices + 2 int8 k32 products per chunk
#define KT (KDIM / BK)       // 128 chunks
#define STAGES 3
#define NTHREADS 128

// smem: row stride 80B (64B data + 16 pad), conflict-free ldmatrix/cp.async
#define ROWB 80
#define A_T (BM * ROWB)                   // 10240 per A tile (fp16 or int8 pair)
#define B_T (BNROWS * ROWB)               // 7680 per B tile
#define STAGE_BYTES (2 * A_T + 2 * B_T)   // 35840
#define SMEM_TOTAL (STAGES * STAGE_BYTES) // 107520 (x2 CTAs = 215KB/SM)

// ---------------- scratch (no cudaMalloc allowed) ----------------
__device__ __half g_A0h[(long)BDIM * KDIM];    // 32MB fp16(X)
__device__ int8_t g_A1q[(long)BDIM * KDIM];    // 16MB s8(57344*(X-fp16 X))
__device__ int8_t g_A0q[(long)BDIM * KDIM];    // 16MB s8(20*X)
__device__ __half g_B0h[(long)NGATE * KDIM];   // 50MB fp16(W^T)
__device__ int8_t g_B0q[(long)NGATE * KDIM];   // 25MB s8(20*W^T)
__device__ int8_t g_B1q[(long)NGATE * KDIM];   // 25MB s8(57344*(W^T-fp16))

// ---------------- helpers ----------------
__device__ __forceinline__ uint32_t smem_u32(const void* p) {
    uint32_t a;
    asm("{ .reg .u64 t; cvta.to.shared.u64 t, %1; cvt.u32.u64 %0, t; }" : "=r"(a) : "l"(p));
    return a;
}
__device__ __forceinline__ void cp16(uint32_t dst, const void* src) {
    asm volatile("cp.async.cg.shared.global [%0], [%1], 16;" :: "r"(dst), "l"(src) : "memory");
}
__device__ __forceinline__ void cp_commit() {
    asm volatile("cp.async.commit_group;" ::: "memory");
}
template <int N>
__device__ __forceinline__ void cp_wait() {
    asm volatile("cp.async.wait_group %0;" :: "n"(N) : "memory");
}
__device__ __forceinline__ void ldsm4(uint32_t& r0, uint32_t& r1, uint32_t& r2, uint32_t& r3,
                                      uint32_t addr) {
    asm volatile("ldmatrix.sync.aligned.m8n8.x4.shared.b16 {%0,%1,%2,%3}, [%4];"
                 : "=r"(r0), "=r"(r1), "=r"(r2), "=r"(r3) : "r"(addr));
}
__device__ __forceinline__ void mma_f32acc(float* c, const uint32_t* a, const uint32_t* b) {
    asm volatile(
        "mma.sync.aligned.m16n8k16.row.col.f32.f16.f16.f32 "
        "{%0,%1,%2,%3}, {%4,%5,%6,%7}, {%8,%9}, {%0,%1,%2,%3};"
        : "+f"(c[0]), "+f"(c[1]), "+f"(c[2]), "+f"(c[3])
        : "r"(a[0]), "r"(a[1]), "r"(a[2]), "r"(a[3]), "r"(b[0]), "r"(b[1]));
}
__device__ __forceinline__ void mma_s8(int* c, const uint32_t* a, const uint32_t* b) {
    asm volatile(
        "mma.sync.aligned.m16n8k32.row.col.s32.s8.s8.s32 "
        "{%0,%1,%2,%3}, {%4,%5,%6,%7}, {%8,%9}, {%0,%1,%2,%3};"
        : "+r"(c[0]), "+r"(c[1]), "+r"(c[2]), "+r"(c[3])
        : "r"(a[0]), "r"(a[1]), "r"(a[2]), "r"(a[3]), "r"(b[0]), "r"(b[1]));
}
__device__ __forceinline__ int8_t q8(float x) {
    int v = __float2int_rn(x);
    v = max(-127, min(127, v));
    return (int8_t)v;
}

// ---------------- prologue: pack & split X = [old_h | input] ----------------
__global__ void pack_split_x(const float* __restrict__ old_h, const float* __restrict__ input,
                             __half* __restrict__ A0h, int8_t* __restrict__ A1q,
                             int8_t* __restrict__ A0q) {
    long i = (long)blockIdx.x * blockDim.x + threadIdx.x;   // float8 units, 4096*512
    int m = (int)(i >> 9);
    int kq = (int)(i & 511);
    const float4* src = (kq < 256) ? &reinterpret_cast<const float4*>(old_h)[(long)m * 512 + 2 * kq]
                                   : &reinterpret_cast<const float4*>(input)[(long)m * 512 + 2 * (kq - 256)];
    float4 v0 = src[0], v1 = src[1];
    float xs[8] = {v0.x, v0.y, v0.z, v0.w, v1.x, v1.y, v1.z, v1.w};
    __half h0[8];
    int8_t r8[8], c8[8];
#pragma unroll
    for (int j = 0; j < 8; j++) {
        float x = xs[j];
        h0[j] = __float2half_rn(x);
        float r = x - __half2float(h0[j]);
        r8[j] = q8(r * SA1F);
        c8[j] = q8(x * SA0F);
    }
    *reinterpret_cast<uint4*>(&A0h[8 * i]) = *reinterpret_cast<uint4*>(h0);
    *reinterpret_cast<uint2*>(&A1q[8 * i]) = *reinterpret_cast<uint2*>(r8);
    *reinterpret_cast<uint2*>(&A0q[8 * i]) = *reinterpret_cast<uint2*>(c8);
}

// ---------------- prologue: transpose & split W -> Wt[n][k] ----------------
__global__ void split_w_kernel(const float* __restrict__ W, __half* __restrict__ B0h,
                               int8_t* __restrict__ B0q, int8_t* __restrict__ B1q) {
    __shared__ float tile[32][33];
    int n0 = blockIdx.x * 32, k0 = blockIdx.y * 32;
    int tid = threadIdx.x;   // 128 threads
#pragma unroll
    for (int e = 0; e < 8; e++) {
        int idx = tid + e * 128;
        int kr = idx >> 5, nc = idx & 31;
        tile[kr][nc] = W[(long)(k0 + kr) * NGATE + n0 + nc];
    }
    __syncthreads();
    int n = tid >> 2, ko = (tid & 3) * 8;
    __half h0[8];
    int8_t q0[8], q1[8];
#pragma unroll
    for (int j = 0; j < 8; j++) {
        float w = tile[ko + j][n];
        h0[j] = __float2half_rn(w);
        float r = w - __half2float(h0[j]);
        q0[j] = q8(w * SA0F);
        q1[j] = q8(r * SA1F);
    }
    long off = (long)(n0 + n) * KDIM + k0 + ko;
    *reinterpret_cast<uint4*>(&B0h[off]) = *reinterpret_cast<uint4*>(h0);
    *reinterpret_cast<uint2*>(&B0q[off]) = *reinterpret_cast<uint2*>(q0);
    *reinterpret_cast<uint2*>(&B1q[off]) = *reinterpret_cast<uint2*>(q1);
}

// ---------------- fused GEMM + LLTM epilogue ----------------
// CTA: 128 rows x 32 state-cols x 3 gates. 4 warps 4(m)x1(n), warp tile 32x96.
__global__ void __launch_bounds__(NTHREADS, 2) lltm_fused_kernel(
    const float* __restrict__ bias, const float* __restrict__ old_c,
    float* __restrict__ out) {
    extern __shared__ char smem[];
    const uint32_t sbase = smem_u32(smem);

    const int tid = threadIdx.x;
    const int warp = tid >> 5, lane = tid & 31;
    const int g = lane >> 2, t4 = lane & 3;
    const long m0 = (long)blockIdx.x * BM;
    const int n0s = blockIdx.y * BNS;        // state-column base (0..2047)

    float acc[2][12][4];
    int acci[2][12][4];
#pragma unroll
    for (int i = 0; i < 2; i++)
#pragma unroll
        for (int j = 0; j < 12; j++)
#pragma unroll
            for (int r = 0; r < 4; r++) {
                acc[i][j][r] = 0.0f;
                acci[i][j][r] = 0;
            }

    // per-lane ldmatrix offsets — identical formula for fp16 and int8 tiles
    const uint32_t a_off = (uint32_t)(warp * 32 + (lane & 15)) * ROWB + ((lane >> 4) << 4);
    const uint32_t b_off =
        (uint32_t)((lane & 7) + ((lane >> 4) << 3)) * ROWB + (((lane >> 3) & 1) << 4);

    // stage layout: sA0h (fp16, 64B/row) | sA8 (bytes 0-31 A1q, 32-63 A0q)
    //             | sB0h (fp16)          | sB8 (bytes 0-31 B0q, 32-63 B1q)
    auto issue_stage = [&](int t) {
        int slot = t % STAGES;
        long kk = (long)t * BK;
        uint32_t sA0h = sbase + slot * STAGE_BYTES;
        uint32_t sA8 = sA0h + A_T;
        uint32_t sB0h = sA8 + A_T;
        uint32_t sB8 = sB0h + B_T;
#pragma unroll
        for (int i = 0; i < 4; i++) {
            int q = tid + i * NTHREADS;
            int row = q >> 2, cw = q & 3;
            long goff = (m0 + row) * KDIM + kk;
            cp16(sA0h + row * ROWB + cw * 16, g_A0h + goff + cw * 8);
            const int8_t* s8p = (cw < 2) ? (g_A1q + goff + cw * 16)
                                         : (g_A0q + goff + (cw - 2) * 16);
            cp16(sA8 + row * ROWB + cw * 16, s8p);
        }
#pragma unroll
        for (int i = 0; i < 3; i++) {
            int q = tid + i * NTHREADS;
            int row = q >> 2, cw = q & 3;        // row 0..95
            long grow = (long)(row >> 5) * SDIM + n0s + (row & 31);
            long goff = grow * KDIM + kk;
            cp16(sB0h + row * ROWB + cw * 16, g_B0h + goff + cw * 8);
            const int8_t* s8p = (cw < 2) ? (g_B0q + goff + cw * 16)
                                         : (g_B1q + goff + (cw - 2) * 16);
            cp16(sB8 + row * ROWB + cw * 16, s8p);
        }
    };

#pragma unroll
    for (int s = 0; s < STAGES - 1; s++) {
        issue_stage(s);
        cp_commit();
    }

    for (int t = 0; t < KT; t++) {
        cp_wait<STAGES - 2>();
        __syncthreads();

        if (t + STAGES - 1 < KT) issue_stage(t + STAGES - 1);
        cp_commit();

        uint32_t sA0h = sbase + (t % STAGES) * STAGE_BYTES;
        uint32_t sA8 = sA0h + A_T;
        uint32_t sB0h = sA8 + A_T;
        uint32_t sB8 = sB0h + B_T;

        uint32_t a[2][4], b[12][2];

        // ---- fp16 main product: 2 k16 slices ----
#pragma unroll
        for (int s = 0; s < 2; s++) {
            const uint32_t ks = (uint32_t)s * 32;
#pragma unroll
            for (int i = 0; i < 2; i++)
                ldsm4(a[i][0], a[i][1], a[i][2], a[i][3],
                      sA0h + a_off + (uint32_t)i * (16 * ROWB) + ks);
#pragma unroll
            for (int jj = 0; jj < 6; jj++)
                ldsm4(b[2 * jj][0], b[2 * jj][1], b[2 * jj + 1][0], b[2 * jj + 1][1],
                      sB0h + b_off + (uint32_t)jj * (16 * ROWB) + ks);
#pragma unroll
            for (int i = 0; i < 2; i++)
#pragma unroll
                for (int j = 0; j < 12; j++) mma_f32acc(acc[i][j], a[i], b[j]);
        }

        // ---- int8 corrections: 2 k32 products into one s32 acc ----
        // P1: A1q x B0q   (A1q at byte 0, B0q at byte 0)
#pragma unroll
        for (int i = 0; i < 2; i++)
            ldsm4(a[i][0], a[i][1], a[i][2], a[i][3],
                  sA8 + a_off + (uint32_t)i * (16 * ROWB));
#pragma unroll
        for (int jj = 0; jj < 6; jj++)
            ldsm4(b[2 * jj][0], b[2 * jj][1], b[2 * jj + 1][0], b[2 * jj + 1][1],
                  sB8 + b_off + (uint32_t)jj * (16 * ROWB));
#pragma unroll
        for (int i = 0; i < 2; i++)
#pragma unroll
            for (int j = 0; j < 12; j++) mma_s8(acci[i][j], a[i], b[j]);
        // P2: A0q x B1q   (A0q at byte 32, B1q at byte 32)
#pragma unroll
        for (int i = 0; i < 2; i++)
            ldsm4(a[i][0], a[i][1], a[i][2], a[i][3],
                  sA8 + a_off + (uint32_t)i * (16 * ROWB) + 32);
#pragma unroll
        for (int jj = 0; jj < 6; jj++)
            ldsm4(b[2 * jj][0], b[2 * jj][1], b[2 * jj + 1][0], b[2 * jj + 1][1],
                  sB8 + b_off + (uint32_t)jj * (16 * ROWB) + 32);
#pragma unroll
        for (int i = 0; i < 2; i++)
#pragma unroll
            for (int j = 0; j < 12; j++) mma_s8(acci[i][j], a[i], b[j]);
    }

    // ---- fused LLTM epilogue: gate = acc + INV_S*acci + bias ----
#pragma unroll
    for (int i = 0; i < 2; i++) {
        long row0 = m0 + warp * 32 + i * 16 + g;
#pragma unroll
        for (int sj = 0; sj < 4; sj++) {
            int col = n0s + sj * 8 + 2 * t4;
            float2 bi = *reinterpret_cast<const float2*>(&bias[col]);
            float2 bo = *reinterpret_cast<const float2*>(&bias[SDIM + col]);
            float2 bc = *reinterpret_cast<const float2*>(&bias[2 * SDIM + col]);
            const float* ai = acc[i][sj];
            const float* ao = acc[i][sj + 4];
            const float* ac = acc[i][sj + 8];
            const int* qi = acci[i][sj];
            const int* qo = acci[i][sj + 4];
            const int* qc = acci[i][sj + 8];
#pragma unroll
            for (int h = 0; h < 2; h++) {        // h=0: row0, h=1: row0+8
                long row = row0 + 8 * h;
                float2 oc = *reinterpret_cast<const float2*>(&old_c[row * SDIM + col]);
                float2 nh, ncell;
#define LANE(f, idx)                                                        \
                {                                                           \
                    float vi = ai[2 * h + idx] + INV_S * (float)qi[2 * h + idx] + bi.f; \
                    float vo = ao[2 * h + idx] + INV_S * (float)qo[2 * h + idx] + bo.f; \
                    float vc = ac[2 * h + idx] + INV_S * (float)qc[2 * h + idx] + bc.f; \
                    float ig = 1.0f / (1.0f + expf(-vi));                   \
                    float og = 1.0f / (1.0f + expf(-vo));                   \
                    float cel = (vc > 0.0f) ? vc : expm1f(vc);              \
                    float cell = oc.f + cel * ig;                           \
                    ncell.f = cell;                                         \
                    nh.f = tanhf(cell) * og;                                \
                }
                LANE(x, 0) LANE(y, 1)
#undef LANE
                *reinterpret_cast<float2*>(&out[row * SDIM + col]) = nh;
                *reinterpret_cast<float2*>(&out[HSIZE + row * SDIM + col]) = ncell;
            }
        }
    }
}

// ---------------- host ----------------
extern "C" void kernel_launch(void* const* d_in, const int* in_sizes, int n_in,
                              void* d_out, int out_size) {
    const float* W     = (const float*)d_in[0];   // (4096, 6144)
    const float* bias  = (const float*)d_in[1];   // (6144,)
    const float* input = (const float*)d_in[2];   // (4096, 2048)
    const float* old_h = (const float*)d_in[3];   // (4096, 2048)
    const float* old_c = (const float*)d_in[4];   // (4096, 2048)
    float* out = (float*)d_out;                   // [new_h | new_cell]

    void *pA0h, *pA1q, *pA0q, *pB0h, *pB0q, *pB1q;
    cudaGetSymbolAddress(&pA0h, g_A0h);
    cudaGetSymbolAddress(&pA1q, g_A1q);
    cudaGetSymbolAddress(&pA0q, g_A0q);
    cudaGetSymbolAddress(&pB0h, g_B0h);
    cudaGetSymbolAddress(&pB0q, g_B0q);
    cudaGetSymbolAddress(&pB1q, g_B1q);

    pack_split_x<<<8192, 256>>>(old_h, input, (__half*)pA0h, (int8_t*)pA1q, (int8_t*)pA0q);
    split_w_kernel<<<dim3(NGATE / 32, KDIM / 32), 128>>>(
        W, (__half*)pB0h, (int8_t*)pB0q, (int8_t*)pB1q);

    cudaFuncSetAttribute(lltm_fused_kernel, cudaFuncAttributeMaxDynamicSharedMemorySize,
                         SMEM_TOTAL);
    lltm_fused_kernel<<<dim3(BDIM / BM, SDIM / BNS), NTHREADS, SMEM_TOTAL>>>(bias, old_c, out);
}

// round 12
// speedup vs baseline: 2.4317x; 2.4317x over previous
#include <cuda_runtime.h>
#include <cuda_fp16.h>
#include <cstdint>
#include <math.h>

// ---------------- problem constants ----------------
#define BDIM   4096          // batch rows
#define KDIM   4096          // F + S
#define NGATE  6144          // 3*S
#define SDIM   2048
#define HSIZE  8388608L      // B*S

// ---------------- tile config: fp16-split 3-product scheme (R10 base) ----------------
// X = A0 + A1 (fp16 + fp16 residual), W^T = B0 + B1.
// main:  A0*B0  -> fp32 accumulators (m16n8k16.f32)
// corr:  A1*B0 + A0*B1 -> fp16 accumulators (m16n8k16.f16)
// gate = acc32 + f16tof32(acc16). Dropped term A1*B1 ~ 2^-22.
#define BM 128
#define BNS 32               // state-cols per CTA; B tile = 3 gates x 32 = 96 rows
#define BNROWS 96
#define BK 32                // 2 k16 slices per chunk
#define KT (KDIM / BK)       // 128 chunks
#define STAGES 3
#define NTHREADS 128

// smem: row stride 80B (64B data + 16 pad), conflict-free ldmatrix/cp.async
#define ROWB 80
#define A_T (BM * ROWB)                   // 10240 per A tile
#define B_T (BNROWS * ROWB)               // 7680 per B tile
#define STAGE_BYTES (2 * A_T + 2 * B_T)   // 35840
#define SMEM_TOTAL (STAGES * STAGE_BYTES) // 107520 (x2 CTAs = 215KB/SM)

// ---------------- scratch (no cudaMalloc allowed) ----------------
__device__ __half g_A0[(long)BDIM * KDIM];    // 32MB  fp16(X)
__device__ __half g_A1[(long)BDIM * KDIM];    // 32MB  fp16(X - A0)
__device__ __half g_B0[(long)NGATE * KDIM];   // 50MB  fp16(W^T)
__device__ __half g_B1[(long)NGATE * KDIM];   // 50MB  fp16(W^T - B0)

// ---------------- helpers ----------------
__device__ __forceinline__ uint32_t smem_u32(const void* p) {
    uint32_t a;
    asm("{ .reg .u64 t; cvta.to.shared.u64 t, %1; cvt.u32.u64 %0, t; }" : "=r"(a) : "l"(p));
    return a;
}
__device__ __forceinline__ void cp16(uint32_t dst, const void* src) {
    asm volatile("cp.async.cg.shared.global [%0], [%1], 16;" :: "r"(dst), "l"(src) : "memory");
}
__device__ __forceinline__ void cp_commit() {
    asm volatile("cp.async.commit_group;" ::: "memory");
}
template <int N>
__device__ __forceinline__ void cp_wait() {
    asm volatile("cp.async.wait_group %0;" :: "n"(N) : "memory");
}
__device__ __forceinline__ void ldsm4(uint32_t& r0, uint32_t& r1, uint32_t& r2, uint32_t& r3,
                                      uint32_t addr) {
    asm volatile("ldmatrix.sync.aligned.m8n8.x4.shared.b16 {%0,%1,%2,%3}, [%4];"
                 : "=r"(r0), "=r"(r1), "=r"(r2), "=r"(r3) : "r"(addr));
}
__device__ __forceinline__ void mma_f32acc(float* c, const uint32_t* a, const uint32_t* b) {
    asm volatile(
        "mma.sync.aligned.m16n8k16.row.col.f32.f16.f16.f32 "
        "{%0,%1,%2,%3}, {%4,%5,%6,%7}, {%8,%9}, {%0,%1,%2,%3};"
        : "+f"(c[0]), "+f"(c[1]), "+f"(c[2]), "+f"(c[3])
        : "r"(a[0]), "r"(a[1]), "r"(a[2]), "r"(a[3]), "r"(b[0]), "r"(b[1]));
}
__device__ __forceinline__ void mma_f16acc(uint32_t* c, const uint32_t* a, const uint32_t* b) {
    asm volatile(
        "mma.sync.aligned.m16n8k16.row.col.f16.f16.f16.f16 "
        "{%0,%1}, {%2,%3,%4,%5}, {%6,%7}, {%0,%1};"
        : "+r"(c[0]), "+r"(c[1])
        : "r"(a[0]), "r"(a[1]), "r"(a[2]), "r"(a[3]), "r"(b[0]), "r"(b[1]));
}
__device__ __forceinline__ void split2h(float x, __half& h0, __half& h1) {
    h0 = __float2half_rn(x);
    h1 = __float2half_rn(x - __half2float(h0));
}

// ---------------- prologue: pack & split X (2 independent units/thread, MLP 4) --------
__global__ void pack_split_x(const float* __restrict__ old_h, const float* __restrict__ input,
                             __half* __restrict__ A0, __half* __restrict__ A1) {
    long i0 = (long)blockIdx.x * blockDim.x + threadIdx.x;   // 0 .. 1048575
#pragma unroll
    for (int u = 0; u < 2; u++) {
        long i = i0 + (long)u * 1048576;     // float8 units, 4096*512 total
        int m = (int)(i >> 9);
        int kq = (int)(i & 511);
        const float4* src = (kq < 256)
            ? &reinterpret_cast<const float4*>(old_h)[(long)m * 512 + 2 * kq]
            : &reinterpret_cast<const float4*>(input)[(long)m * 512 + 2 * (kq - 256)];
        float4 v0 = src[0], v1 = src[1];
        __half h0[8], h1[8];
        split2h(v0.x, h0[0], h1[0]); split2h(v0.y, h0[1], h1[1]);
        split2h(v0.z, h0[2], h1[2]); split2h(v0.w, h0[3], h1[3]);
        split2h(v1.x, h0[4], h1[4]); split2h(v1.y, h0[5], h1[5]);
        split2h(v1.z, h0[6], h1[6]); split2h(v1.w, h0[7], h1[7]);
        *reinterpret_cast<uint4*>(&A0[8 * i]) = *reinterpret_cast<uint4*>(h0);
        *reinterpret_cast<uint4*>(&A1[8 * i]) = *reinterpret_cast<uint4*>(h1);
    }
}

// ---------------- prologue: transpose & split W (2 k-tiles/block, 16 loads in flight) --
__global__ void split_w_kernel(const float* __restrict__ W,
                               __half* __restrict__ B0, __half* __restrict__ B1) {
    __shared__ float tile[2][32][33];
    int n0 = blockIdx.x * 32, k0 = blockIdx.y * 64;
    int tid = threadIdx.x;   // 128 threads
#pragma unroll
    for (int e = 0; e < 8; e++) {
        int idx = tid + e * 128;
        int kr = idx >> 5, nc = idx & 31;
        tile[0][kr][nc] = W[(long)(k0 + kr) * NGATE + n0 + nc];
        tile[1][kr][nc] = W[(long)(k0 + 32 + kr) * NGATE + n0 + nc];
    }
    __syncthreads();
    int n = tid >> 2, ko = (tid & 3) * 8;
#pragma unroll
    for (int b = 0; b < 2; b++) {
        __half h0[8], h1[8];
#pragma unroll
        for (int j = 0; j < 8; j++)
            split2h(tile[b][ko + j][n], h0[j], h1[j]);
        long off = (long)(n0 + n) * KDIM + k0 + b * 32 + ko;
        *reinterpret_cast<uint4*>(&B0[off]) = *reinterpret_cast<uint4*>(h0);
        *reinterpret_cast<uint4*>(&B1[off]) = *reinterpret_cast<uint4*>(h1);
    }
}

// ---------------- fused GEMM + LLTM epilogue ----------------
// CTA: 128 rows x 32 state-cols x 3 gates. 4 warps 4(m)x1(n), warp tile 32x96.
__global__ void __launch_bounds__(NTHREADS, 2) lltm_fused_kernel(
    const float* __restrict__ bias, const float* __restrict__ old_c,
    float* __restrict__ out) {
    extern __shared__ char smem[];
    const uint32_t sbase = smem_u32(smem);

    const int tid = threadIdx.x;
    const int warp = tid >> 5, lane = tid & 31;
    const int g = lane >> 2, t4 = lane & 3;
    const long m0 = (long)blockIdx.x * BM;
    const int n0s = blockIdx.y * BNS;        // state-column base (0..2047)

    float acc[2][12][4];
    uint32_t acch[2][12][2];
#pragma unroll
    for (int i = 0; i < 2; i++)
#pragma unroll
        for (int j = 0; j < 12; j++) {
#pragma unroll
            for (int r = 0; r < 4; r++) acc[i][j][r] = 0.0f;
            acch[i][j][0] = 0u;
            acch[i][j][1] = 0u;
        }

    const uint32_t a_off = (uint32_t)(warp * 32 + (lane & 15)) * ROWB + ((lane >> 4) << 4);
    const uint32_t b_off =
        (uint32_t)((lane & 7) + ((lane >> 4) << 3)) * ROWB + (((lane >> 3) & 1) << 4);

    auto issue_stage = [&](int t) {
        int slot = t % STAGES;
        long kk = (long)t * BK;
        uint32_t sA0 = sbase + slot * STAGE_BYTES;
        uint32_t sA1 = sA0 + A_T;
        uint32_t sB0 = sA1 + A_T;
        uint32_t sB1 = sB0 + B_T;
#pragma unroll
        for (int i = 0; i < 4; i++) {
            int q = tid + i * NTHREADS;
            int row = q >> 2, cw = q & 3;
            long goff = (m0 + row) * KDIM + kk + cw * 8;
            cp16(sA0 + row * ROWB + cw * 16, g_A0 + goff);
            cp16(sA1 + row * ROWB + cw * 16, g_A1 + goff);
        }
#pragma unroll
        for (int i = 0; i < 3; i++) {
            int q = tid + i * NTHREADS;
            int row = q >> 2, cw = q & 3;        // row 0..95
            long grow = (long)(row >> 5) * SDIM + n0s + (row & 31);
            long goff = grow * KDIM + kk + cw * 8;
            cp16(sB0 + row * ROWB + cw * 16, g_B0 + goff);
            cp16(sB1 + row * ROWB + cw * 16, g_B1 + goff);
        }
    };

#pragma unroll
    for (int s = 0; s < STAGES - 1; s++) {
        issue_stage(s);
        cp_commit();
    }

    for (int t = 0; t < KT; t++) {
        cp_wait<STAGES - 2>();
        __syncthreads();

        if (t + STAGES - 1 < KT) issue_stage(t + STAGES - 1);
        cp_commit();

        uint32_t sA0 = sbase + (t % STAGES) * STAGE_BYTES;
        uint32_t sA1 = sA0 + A_T;
        uint32_t sB0 = sA1 + A_T;
        uint32_t sB1 = sB0 + B_T;

#pragma unroll
        for (int s = 0; s < 2; s++) {            // 2 k16 slices per chunk
            const uint32_t ks = (uint32_t)s * 32;
            uint32_t a0[2][4], a1[2][4], b[12][2];
#pragma unroll
            for (int i = 0; i < 2; i++) {
                ldsm4(a0[i][0], a0[i][1], a0[i][2], a0[i][3],
                      sA0 + a_off + (uint32_t)i * (16 * ROWB) + ks);
                ldsm4(a1[i][0], a1[i][1], a1[i][2], a1[i][3],
                      sA1 + a_off + (uint32_t)i * (16 * ROWB) + ks);
            }
            // B0: main (fp32 acc) + correction A1*B0 (fp16 acc)
#pragma unroll
            for (int jj = 0; jj < 6; jj++)
                ldsm4(b[2 * jj][0], b[2 * jj][1], b[2 * jj + 1][0], b[2 * jj + 1][1],
                      sB0 + b_off + (uint32_t)jj * (16 * ROWB) + ks);
#pragma unroll
            for (int i = 0; i < 2; i++)
#pragma unroll
                for (int j = 0; j < 12; j++) mma_f32acc(acc[i][j], a0[i], b[j]);
#pragma unroll
            for (int i = 0; i < 2; i++)
#pragma unroll
                for (int j = 0; j < 12; j++) mma_f16acc(acch[i][j], a1[i], b[j]);
            // B1: correction A0*B1 (fp16 acc), reuse b regs
#pragma unroll
            for (int jj = 0; jj < 6; jj++)
                ldsm4(b[2 * jj][0], b[2 * jj][1], b[2 * jj + 1][0], b[2 * jj + 1][1],
                      sB1 + b_off + (uint32_t)jj * (16 * ROWB) + ks);
#pragma unroll
            for (int i = 0; i < 2; i++)
#pragma unroll
                for (int j = 0; j < 12; j++) mma_f16acc(acch[i][j], a0[i], b[j]);
        }
    }

    // ---- fused LLTM epilogue: gate = acc32 + f16tof32(acc16), fast-math transcend. ----
#pragma unroll
    for (int i = 0; i < 2; i++) {
        long row0 = m0 + warp * 32 + i * 16 + g;
#pragma unroll
        for (int sj = 0; sj < 4; sj++) {
            int col = n0s + sj * 8 + 2 * t4;
            float2 bi = *reinterpret_cast<const float2*>(&bias[col]);
            float2 bo = *reinterpret_cast<const float2*>(&bias[SDIM + col]);
            float2 bc = *reinterpret_cast<const float2*>(&bias[2 * SDIM + col]);
            const float* ai = acc[i][sj];
            const float* ao = acc[i][sj + 4];
            const float* ac = acc[i][sj + 8];
            const uint32_t* hi_ = acch[i][sj];
            const uint32_t* ho_ = acch[i][sj + 4];
            const uint32_t* hc_ = acch[i][sj + 8];
#pragma unroll
            for (int h = 0; h < 2; h++) {        // h=0: row0, h=1: row0+8
                long row = row0 + 8 * h;
                float2 ci = __half22float2(*reinterpret_cast<const __half2*>(&hi_[h]));
                float2 co = __half22float2(*reinterpret_cast<const __half2*>(&ho_[h]));
                float2 cc2 = __half22float2(*reinterpret_cast<const __half2*>(&hc_[h]));
                float2 oc = *reinterpret_cast<const float2*>(&old_c[row * SDIM + col]);
                float2 nh, ncell;
#define LANE(f, idx)                                                    \
                {                                                       \
                    float vi = ai[2 * h + idx] + ci.f + bi.f;           \
                    float vo = ao[2 * h + idx] + co.f + bo.f;           \
                    float vc = ac[2 * h + idx] + cc2.f + bc.f;          \
                    float ig = 1.0f / (1.0f + __expf(-vi));             \
                    float og = 1.0f / (1.0f + __expf(-vo));             \
                    float cel = (vc > 0.0f) ? vc : (__expf(vc) - 1.0f); \
                    float cell = oc.f + cel * ig;                       \
                    ncell.f = cell;                                     \
                    nh.f = tanhf(cell) * og;                            \
                }
                LANE(x, 0) LANE(y, 1)
#undef LANE
                *reinterpret_cast<float2*>(&out[row * SDIM + col]) = nh;
                *reinterpret_cast<float2*>(&out[HSIZE + row * SDIM + col]) = ncell;
            }
        }
    }
}

// ---------------- host ----------------
extern "C" void kernel_launch(void* const* d_in, const int* in_sizes, int n_in,
                              void* d_out, int out_size) {
    const float* W     = (const float*)d_in[0];   // (4096, 6144)
    const float* bias  = (const float*)d_in[1];   // (6144,)
    const float* input = (const float*)d_in[2];   // (4096, 2048)
    const float* old_h = (const float*)d_in[3];   // (4096, 2048)
    const float* old_c = (const float*)d_in[4];   // (4096, 2048)
    float* out = (float*)d_out;                   // [new_h | new_cell]

    void *pA0, *pA1, *pB0, *pB1;
    cudaGetSymbolAddress(&pA0, g_A0);
    cudaGetSymbolAddress(&pA1, g_A1);
    cudaGetSymbolAddress(&pB0, g_B0);
    cudaGetSymbolAddress(&pB1, g_B1);

    pack_split_x<<<4096, 256>>>(old_h, input, (__half*)pA0, (__half*)pA1);
    split_w_kernel<<<dim3(NGATE / 32, KDIM / 64), 128>>>(W, (__half*)pB0, (__half*)pB1);

    cudaFuncSetAttribute(lltm_fused_kernel, cudaFuncAttributeMaxDynamicSharedMemorySize,
                         SMEM_TOTAL);
    lltm_fused_kernel<<<dim3(BDIM / BM, SDIM / BNS), NTHREADS, SMEM_TOTAL>>>(bias, old_c, out);
}